// round 14
// baseline (speedup 1.0000x reference)
#include <cuda_runtime.h>
#include <math.h>
#include <cstdint>

// ---------------------------------------------------------------------------
// PreQ round 14: round-13 (best: 206.9us) + merged single prep launch +
// u-outer MMA ordering (same-acc reuse distance 2 -> 14 instructions).
//  - A smem rows padded to 36 floats (144B), no swizzle, LDS.32 imm offsets
//  - A fragments raw fp32 bits (HW tf32 truncation), W RN frag images
//  - 3-stage cp.async ring; L1 y-interleaved N-split; L3 fused tail
// ---------------------------------------------------------------------------

#define MROWS 131072   // 2 * 65536
#define ASTR  36       // A smem row stride in floats (144B)

__device__ float g_h1[(size_t)MROWS * 200];
__device__ float g_h2[(size_t)MROWS * 100];
__device__ __align__(16) unsigned char g_w1f[224 * 1280];
__device__ __align__(16) unsigned char g_w2f[112 * 896];
__device__ __align__(16) unsigned char g_w3f[64 * 512];

// ---------------- helpers ----------------
__device__ __forceinline__ uint32_t smem_u32(const void* p) {
    uint32_t a;
    asm("{ .reg .u64 t; cvta.to.shared.u64 t, %1; cvt.u32.u64 %0, t; }"
        : "=r"(a) : "l"(p));
    return a;
}
__device__ __forceinline__ void cpa16(uint32_t dst, const void* src) {
    asm volatile("cp.async.cg.shared.global [%0], [%1], 16;"
                 :: "r"(dst), "l"(src) : "memory");
}
__device__ __forceinline__ void cpa16z(uint32_t dst, const void* src, int sz) {
    asm volatile("cp.async.cg.shared.global [%0], [%1], 16, %2;"
                 :: "r"(dst), "l"(src), "r"(sz) : "memory");
}
#define CP_COMMIT() asm volatile("cp.async.commit_group;" ::: "memory")
#define CP_WAIT0()  asm volatile("cp.async.wait_group 0;" ::: "memory")
#define CP_WAIT1()  asm volatile("cp.async.wait_group 1;" ::: "memory")

__device__ __forceinline__ uint32_t to_tf32(float f) {
    uint32_t r;
    asm("cvt.rna.tf32.f32 %0, %1;" : "=r"(r) : "f"(f));
    return r;
}
__device__ __forceinline__ void mma_tf32(float c[4],
                                         uint32_t a0, uint32_t a1,
                                         uint32_t a2, uint32_t a3,
                                         uint32_t b0, uint32_t b1) {
    asm volatile(
        "mma.sync.aligned.m16n8k8.row.col.f32.tf32.tf32.f32 "
        "{%0,%1,%2,%3}, {%4,%5,%6,%7}, {%8,%9}, {%0,%1,%2,%3};"
        : "+f"(c[0]), "+f"(c[1]), "+f"(c[2]), "+f"(c[3])
        : "r"(a0), "r"(a1), "r"(a2), "r"(a3), "r"(b0), "r"(b1));
}

// ---------------------------------------------------------------------------
// Merged prep: all three W frag images in ONE launch.
// Work item f spans [0, 224*20 + 112*14 + 64*8).
// ---------------------------------------------------------------------------
__device__ __forceinline__ void prep_one(const float* S, unsigned char* D,
                                         int src_rows, int K, int nblk, int f) {
    int row = f / nblk, eb = f - row * nblk;
    int k0 = eb * 16;
    float v[16];
    #pragma unroll
    for (int i = 0; i < 16; i++) v[i] = 0.f;
    if (row < src_rows) {
        #pragma unroll
        for (int i = 0; i < 4; i++) {
            int k = k0 + i * 4;
            if (k < K) {
                float4 q = *(const float4*)(S + (size_t)row * K + k);
                v[i * 4 + 0] = q.x; v[i * 4 + 1] = q.y;
                v[i * 4 + 2] = q.z; v[i * 4 + 3] = q.w;
            }
        }
    }
    uint32_t u[16];
    #pragma unroll
    for (int i = 0; i < 16; i++) u[i] = to_tf32(v[i]);
    unsigned char* dst = D + (size_t)row * (nblk * 64) + (size_t)eb * 64;
    #pragma unroll
    for (int tp = 0; tp < 4; tp++)
        *(uint4*)(dst + tp * 16) =
            make_uint4(u[tp], u[tp + 4], u[tp + 8], u[tp + 12]);
}

__global__ void prep_all(const float* __restrict__ W1,
                         const float* __restrict__ W2,
                         const float* __restrict__ W3,
                         unsigned char* __restrict__ w1f,
                         unsigned char* __restrict__ w2f,
                         unsigned char* __restrict__ w3f) {
    constexpr int N1 = 224 * 20;            // 4480
    constexpr int N2 = N1 + 112 * 14;       // 6048
    constexpr int N3 = N2 + 64 * 8;         // 6560
    int f = blockIdx.x * blockDim.x + threadIdx.x;
    if (f < N1)      prep_one(W1, w1f, 200, 300, 20, f);
    else if (f < N2) prep_one(W2, w2f, 100, 200, 14, f - N1);
    else if (f < N3) prep_one(W3, w3f, 50,  100, 8,  f - N2);
}

// ---------------- quantum math (verified rounds 1-13) ----------------
__device__ __forceinline__ float2 cadd(float2 a, float2 b) {
    return make_float2(a.x + b.x, a.y + b.y);
}
__device__ __forceinline__ float2 csc(float s, float2 a) {
    return make_float2(s * a.x, s * a.y);
}
__device__ __forceinline__ float2 cni(float s, float2 a) {
    return make_float2(s * a.y, -s * a.x);
}
__device__ void applyU(const float* __restrict__ p, float2 x[4]) {
    float c4, s4;
    __sincosf(0.5f * p[4], &s4, &c4);
    float2 y1 = make_float2(c4 * x[1].x + s4 * x[3].y,
                            c4 * x[1].y - s4 * x[3].x);
    float2 y3 = make_float2(s4 * x[1].y + c4 * x[3].x,
                           -s4 * x[1].x + c4 * x[3].y);
    x[1] = y1; x[3] = y3;
    float c2, s2, c3, s3;
    __sincosf(0.5f * p[2], &s2, &c2);
    __sincosf(0.5f * p[3], &s3, &c3);
    float2 t00 = cadd(csc(c3, x[0]), csc(-s3, x[1]));
    float2 t01 = cadd(csc(s3, x[0]), csc( c3, x[1]));
    float2 t10 = cadd(csc(c3, x[2]), csc(-s3, x[3]));
    float2 t11 = cadd(csc(s3, x[2]), csc( c3, x[3]));
    x[0] = cadd(csc(c2, t00), csc(-s2, t10));
    x[1] = cadd(csc(c2, t01), csc(-s2, t11));
    x[2] = cadd(csc(s2, t00), csc( c2, t10));
    x[3] = cadd(csc(s2, t01), csc( c2, t11));
    float c1, s1;
    __sincosf(0.5f * p[1], &s1, &c1);
    float2 u00 = cadd(csc(c1, x[0]), cni(s1, x[1]));
    float2 u01 = cadd(cni(s1, x[0]), csc(c1, x[1]));
    float2 u10 = cadd(csc(c1, x[2]), cni(s1, x[3]));
    float2 u11 = cadd(cni(s1, x[2]), csc(c1, x[3]));
    x[0] = cadd(csc(c1, u00), cni(s1, u10));
    x[1] = cadd(csc(c1, u01), cni(s1, u11));
    x[2] = cadd(cni(s1, u00), csc(c1, u10));
    x[3] = cadd(cni(s1, u01), csc(c1, u11));
}
__device__ __forceinline__ float fidelity_from(const float* l1, const float* l2) {
    float2 s1[4] = {make_float2(1.f, 0.f), make_float2(0.f, 0.f),
                    make_float2(0.f, 0.f), make_float2(0.f, 0.f)};
    applyU(l1, s1);
    applyU(l1 + 5, s1);
    float2 s2[4] = {make_float2(1.f, 0.f), make_float2(0.f, 0.f),
                    make_float2(0.f, 0.f), make_float2(0.f, 0.f)};
    applyU(l2, s2);
    applyU(l2 + 5, s2);
    float re = 0.f, im = 0.f;
    #pragma unroll
    for (int i = 0; i < 4; i++) {
        re += s2[i].x * s1[i].x + s2[i].y * s1[i].y;
        im += s2[i].x * s1[i].y - s2[i].y * s1[i].x;
    }
    return re * re + im * im;
}

// ---------------------------------------------------------------------------
// tf32 GEMM (round-13 structure, u-outer MMA order).
// ---------------------------------------------------------------------------
template<int NWT, int OMODE, bool YSPLIT>
__global__ __launch_bounds__(256, 2)
void gemm_tf32(const float* __restrict__ A,
               const unsigned char* __restrict__ Wf,
               const float* __restrict__ bias, void* __restrict__ Out,
               int Ntrue, int K, int nch, int w_rowb,
               const float* __restrict__ W4, const float* __restrict__ b4) {
    extern __shared__ __align__(16) char sm[];
    constexpr int NTC   = NWT * 16;
    constexpr int ABY   = 128 * ASTR * 4;     // 18432
    constexpr int STAGE = ABY + NTC * 128;
    constexpr int CSS   = 68;

    const uint32_t sb = smem_u32(sm);
    const int tid  = threadIdx.x;
    const int wid  = tid >> 5;
    const int lane = tid & 31;
    const int g    = lane >> 2;
    const int t    = lane & 3;
    const int mw   = wid & 3;
    const int nw   = wid >> 2;
    const int bx   = blockIdx.x;
    const size_t m0 = (size_t)(YSPLIT ? (bx >> 1) : bx) * 128;
    const int n0   = YSPLIT ? (bx & 1) * NTC : 0;

    float acc[2][NWT][4];
    #pragma unroll
    for (int mt = 0; mt < 2; mt++)
        #pragma unroll
        for (int j = 0; j < NWT; j++)
            #pragma unroll
            for (int p = 0; p < 4; p++) acc[mt][j][p] = 0.f;

    auto stage = [&](int c, int slot) {
        const uint32_t bufb = sb + slot * STAGE;
        #pragma unroll
        for (int i = 0; i < 4; i++) {
            int f = tid + i * 256;
            int row = f >> 3, j = f & 7;
            int k0 = c * 32 + j * 4;
            int sz = (k0 + 4 <= K) ? 16 : 0;
            const float* src = A + (m0 + row) * (size_t)K + (sz ? k0 : 0);
            cpa16z(bufb + row * 144 + j * 16, src, sz);
        }
        #pragma unroll
        for (int i = 0; i < (NTC * 8 + 255) / 256; i++) {
            int f = tid + i * 256;
            if (f < NTC * 8) {
                int row = f >> 3, e = f & 7;
                cpa16(bufb + ABY + row * 128 + 16 * (e ^ ((row & 1) * 4)),
                      Wf + (size_t)(n0 + row) * w_rowb + c * 128 + e * 16);
            }
        }
    };
    auto compute = [&](int slot) {
        const uint32_t* Asu = (const uint32_t*)(sm + slot * STAGE);
        const char*     Ws  = sm + slot * STAGE + ABY;
        const uint32_t* rb0 = Asu + (mw * 32 +      g) * ASTR + t;
        const uint32_t* rb1 = Asu + (mw * 32 +  8 + g) * ASTR + t;
        const uint32_t* rb2 = Asu + (mw * 32 + 16 + g) * ASTR + t;
        const uint32_t* rb3 = Asu + (mw * 32 + 24 + g) * ASTR + t;
        #pragma unroll
        for (int s = 0; s < 2; s++) {
            uint32_t ua[4][4];
            #pragma unroll
            for (int q = 0; q < 4; q++) {
                ua[0][q] = rb0[16 * s + 4 * q];
                ua[1][q] = rb1[16 * s + 4 * q];
                ua[2][q] = rb2[16 * s + 4 * q];
                ua[3][q] = rb3[16 * s + 4 * q];
            }
            uint4 bbv[NWT];
            #pragma unroll
            for (int j = 0; j < NWT; j++) {
                int wr = (nw * NWT + j) * 8 + g;
                bbv[j] = *(const uint4*)(Ws + wr * 128 +
                                         16 * ((s * 4 + t) ^ ((wr & 1) * 4)));
            }
            // u-outer ordering: same-acc reuse distance = 2*NWT instructions
            #pragma unroll
            for (int j = 0; j < NWT; j++) {
                mma_tf32(acc[0][j], ua[0][0], ua[1][0], ua[0][1], ua[1][1],
                         bbv[j].x, bbv[j].y);
                mma_tf32(acc[1][j], ua[2][0], ua[3][0], ua[2][1], ua[3][1],
                         bbv[j].x, bbv[j].y);
            }
            #pragma unroll
            for (int j = 0; j < NWT; j++) {
                mma_tf32(acc[0][j], ua[0][2], ua[1][2], ua[0][3], ua[1][3],
                         bbv[j].z, bbv[j].w);
                mma_tf32(acc[1][j], ua[2][2], ua[3][2], ua[2][3], ua[3][3],
                         bbv[j].z, bbv[j].w);
            }
        }
    };

    stage(0, 0); CP_COMMIT();
    stage(1, 1); CP_COMMIT();
    for (int c = 0; c < nch; ++c) {
        if (c + 1 < nch) { CP_WAIT1(); } else { CP_WAIT0(); }
        __syncthreads();
        compute(c - (c / 3) * 3);
        if (c + 2 < nch) { stage(c + 2, (c + 2) % 3); CP_COMMIT(); }
    }
    __syncthreads();

    if constexpr (OMODE == 0) {
        float* C = (float*)Out;
        #pragma unroll
        for (int mt = 0; mt < 2; mt++) {
            const size_t r = m0 + mw * 32 + mt * 16 + g;
            #pragma unroll
            for (int j = 0; j < NWT; j++) {
                int n = n0 + (nw * NWT + j) * 8 + 2 * t;
                if (n < Ntrue) {
                    float2 b2 = *(const float2*)(bias + n);
                    float v0 = fmaxf(acc[mt][j][0] + b2.x, 0.f);
                    float v1 = fmaxf(acc[mt][j][1] + b2.y, 0.f);
                    float v2 = fmaxf(acc[mt][j][2] + b2.x, 0.f);
                    float v3 = fmaxf(acc[mt][j][3] + b2.y, 0.f);
                    *(float2*)(C + r * Ntrue + n)       = make_float2(v0, v1);
                    *(float2*)(C + (r + 8) * Ntrue + n) = make_float2(v2, v3);
                }
            }
        }
    } else {
        float* Cs = (float*)sm;
        #pragma unroll
        for (int mt = 0; mt < 2; mt++) {
            int r = mw * 32 + mt * 16 + g;
            #pragma unroll
            for (int j = 0; j < NWT; j++) {
                int nl = (nw * NWT + j) * 8 + 2 * t;
                float bx2 = (nl     < Ntrue) ? bias[nl]     : 0.f;
                float by2 = (nl + 1 < Ntrue) ? bias[nl + 1] : 0.f;
                float v0 = fmaxf(acc[mt][j][0] + bx2, 0.f);
                float v1 = fmaxf(acc[mt][j][1] + by2, 0.f);
                float v2 = fmaxf(acc[mt][j][2] + bx2, 0.f);
                float v3 = fmaxf(acc[mt][j][3] + by2, 0.f);
                *(float2*)(Cs + r * CSS + nl)       = make_float2(v0, v1);
                *(float2*)(Cs + (r + 8) * CSS + nl) = make_float2(v2, v3);
            }
        }
        float* w4s = (float*)(sm + 128 * CSS * 4);
        float* b4s = w4s + 500;
        float* Ls  = (float*)(sm + 128 * CSS * 4 + 2048);
        for (int i = tid; i < 500; i += 256) w4s[i] = W4[i];
        if (tid < 10) b4s[tid] = b4[tid];
        __syncthreads();

        if (tid < 128) {
            float l[10];
            #pragma unroll
            for (int j = 0; j < 10; j++) l[j] = b4s[j];
            #pragma unroll 5
            for (int k = 0; k < 50; k++) {
                float hv = Cs[tid * CSS + k];
                #pragma unroll
                for (int j = 0; j < 10; j++) l[j] = fmaf(w4s[j * 50 + k], hv, l[j]);
            }
            #pragma unroll
            for (int j = 0; j < 10; j++) Ls[tid * 11 + j] = l[j];
        }
        __syncthreads();
        if (tid < 64) {
            ((float*)Out)[(size_t)blockIdx.x * 64 + tid] =
                fidelity_from(Ls + 2 * tid * 11, Ls + (2 * tid + 1) * 11);
        }
    }
}

// ---------------------------------------------------------------------------
extern "C" void kernel_launch(void* const* d_in, const int* in_sizes, int n_in,
                              void* d_out, int out_size) {
    const float* x  = (const float*)d_in[0];
    const float* W1 = (const float*)d_in[1];
    const float* b1 = (const float*)d_in[2];
    const float* W2 = (const float*)d_in[3];
    const float* b2 = (const float*)d_in[4];
    const float* W3 = (const float*)d_in[5];
    const float* b3 = (const float*)d_in[6];
    const float* W4 = (const float*)d_in[7];
    const float* b4 = (const float*)d_in[8];

    float *h1, *h2;
    unsigned char *w1f, *w2f, *w3f;
    cudaGetSymbolAddress((void**)&h1,  g_h1);
    cudaGetSymbolAddress((void**)&h2,  g_h2);
    cudaGetSymbolAddress((void**)&w1f, g_w1f);
    cudaGetSymbolAddress((void**)&w2f, g_w2f);
    cudaGetSymbolAddress((void**)&w3f, g_w3f);

    // Single merged prep launch (6560 work items)
    prep_all<<<(6560 + 255) / 256, 256>>>(W1, W2, W3, w1f, w2f, w3f);

    constexpr int SM12 = 3 * (128 * 144 + 112 * 128);  // 98304
    constexpr int SM3  = 3 * (128 * 144 + 64  * 128);  // 79872
    cudaFuncSetAttribute(gemm_tf32<7, 0, true>,
                         cudaFuncAttributeMaxDynamicSharedMemorySize, SM12);
    cudaFuncSetAttribute(gemm_tf32<7, 0, false>,
                         cudaFuncAttributeMaxDynamicSharedMemorySize, SM12);
    cudaFuncSetAttribute(gemm_tf32<4, 2, false>,
                         cudaFuncAttributeMaxDynamicSharedMemorySize, SM3);

    const int MT = MROWS / 128;   // 1024
    gemm_tf32<7, 0, true ><<<MT * 2, 256, SM12>>>(x,  w1f, b1, h1,
                                                  200, 300, 10, 1280, W4, b4);
    gemm_tf32<7, 0, false><<<MT,     256, SM12>>>(h1, w2f, b2, h2,
                                                  100, 200, 7, 896, W4, b4);
    gemm_tf32<4, 2, false><<<MT,     256, SM3 >>>(h2, w3f, b3, d_out,
                                                  50, 100, 4, 512, W4, b4);
}

// round 15
// speedup vs baseline: 1.1271x; 1.1271x over previous
#include <cuda_runtime.h>
#include <math.h>
#include <cstdint>

// ---------------------------------------------------------------------------
// PreQ round 15: round-13 GEMM verbatim (best: 206.9us) + single merged
// prep launch (the one R14 change that was sound).
//  - A smem rows padded to 36 floats (144B), no swizzle, LDS.32 imm offsets
//  - A fragments raw fp32 bits (HW tf32 truncation), W RN frag images
//  - 3-stage cp.async ring; L1 y-interleaved N-split; L3 fused tail
// ---------------------------------------------------------------------------

#define MROWS 131072   // 2 * 65536
#define ASTR  36       // A smem row stride in floats (144B)

__device__ float g_h1[(size_t)MROWS * 200];
__device__ float g_h2[(size_t)MROWS * 100];
__device__ __align__(16) unsigned char g_w1f[224 * 1280];
__device__ __align__(16) unsigned char g_w2f[112 * 896];
__device__ __align__(16) unsigned char g_w3f[64 * 512];

// ---------------- helpers ----------------
__device__ __forceinline__ uint32_t smem_u32(const void* p) {
    uint32_t a;
    asm("{ .reg .u64 t; cvta.to.shared.u64 t, %1; cvt.u32.u64 %0, t; }"
        : "=r"(a) : "l"(p));
    return a;
}
__device__ __forceinline__ void cpa16(uint32_t dst, const void* src) {
    asm volatile("cp.async.cg.shared.global [%0], [%1], 16;"
                 :: "r"(dst), "l"(src) : "memory");
}
__device__ __forceinline__ void cpa16z(uint32_t dst, const void* src, int sz) {
    asm volatile("cp.async.cg.shared.global [%0], [%1], 16, %2;"
                 :: "r"(dst), "l"(src), "r"(sz) : "memory");
}
#define CP_COMMIT() asm volatile("cp.async.commit_group;" ::: "memory")
#define CP_WAIT0()  asm volatile("cp.async.wait_group 0;" ::: "memory")
#define CP_WAIT1()  asm volatile("cp.async.wait_group 1;" ::: "memory")

__device__ __forceinline__ uint32_t to_tf32(float f) {
    uint32_t r;
    asm("cvt.rna.tf32.f32 %0, %1;" : "=r"(r) : "f"(f));
    return r;
}
__device__ __forceinline__ void mma_tf32(float c[4],
                                         uint32_t a0, uint32_t a1,
                                         uint32_t a2, uint32_t a3,
                                         uint32_t b0, uint32_t b1) {
    asm volatile(
        "mma.sync.aligned.m16n8k8.row.col.f32.tf32.tf32.f32 "
        "{%0,%1,%2,%3}, {%4,%5,%6,%7}, {%8,%9}, {%0,%1,%2,%3};"
        : "+f"(c[0]), "+f"(c[1]), "+f"(c[2]), "+f"(c[3])
        : "r"(a0), "r"(a1), "r"(a2), "r"(a3), "r"(b0), "r"(b1));
}

// ---------------------------------------------------------------------------
// Merged prep: all three W frag images in ONE launch.
// ---------------------------------------------------------------------------
__device__ __forceinline__ void prep_one(const float* S, unsigned char* D,
                                         int src_rows, int K, int nblk, int f) {
    int row = f / nblk, eb = f - row * nblk;
    int k0 = eb * 16;
    float v[16];
    #pragma unroll
    for (int i = 0; i < 16; i++) v[i] = 0.f;
    if (row < src_rows) {
        #pragma unroll
        for (int i = 0; i < 4; i++) {
            int k = k0 + i * 4;
            if (k < K) {
                float4 q = *(const float4*)(S + (size_t)row * K + k);
                v[i * 4 + 0] = q.x; v[i * 4 + 1] = q.y;
                v[i * 4 + 2] = q.z; v[i * 4 + 3] = q.w;
            }
        }
    }
    uint32_t u[16];
    #pragma unroll
    for (int i = 0; i < 16; i++) u[i] = to_tf32(v[i]);
    unsigned char* dst = D + (size_t)row * (nblk * 64) + (size_t)eb * 64;
    #pragma unroll
    for (int tp = 0; tp < 4; tp++)
        *(uint4*)(dst + tp * 16) =
            make_uint4(u[tp], u[tp + 4], u[tp + 8], u[tp + 12]);
}

__global__ void prep_all(const float* __restrict__ W1,
                         const float* __restrict__ W2,
                         const float* __restrict__ W3,
                         unsigned char* __restrict__ w1f,
                         unsigned char* __restrict__ w2f,
                         unsigned char* __restrict__ w3f) {
    constexpr int N1 = 224 * 20;            // 4480
    constexpr int N2 = N1 + 112 * 14;       // 6048
    constexpr int N3 = N2 + 64 * 8;         // 6560
    int f = blockIdx.x * blockDim.x + threadIdx.x;
    if (f < N1)      prep_one(W1, w1f, 200, 300, 20, f);
    else if (f < N2) prep_one(W2, w2f, 100, 200, 14, f - N1);
    else if (f < N3) prep_one(W3, w3f, 50,  100, 8,  f - N2);
}

// ---------------- quantum math (verified rounds 1-14) ----------------
__device__ __forceinline__ float2 cadd(float2 a, float2 b) {
    return make_float2(a.x + b.x, a.y + b.y);
}
__device__ __forceinline__ float2 csc(float s, float2 a) {
    return make_float2(s * a.x, s * a.y);
}
__device__ __forceinline__ float2 cni(float s, float2 a) {
    return make_float2(s * a.y, -s * a.x);
}
__device__ void applyU(const float* __restrict__ p, float2 x[4]) {
    float c4, s4;
    __sincosf(0.5f * p[4], &s4, &c4);
    float2 y1 = make_float2(c4 * x[1].x + s4 * x[3].y,
                            c4 * x[1].y - s4 * x[3].x);
    float2 y3 = make_float2(s4 * x[1].y + c4 * x[3].x,
                           -s4 * x[1].x + c4 * x[3].y);
    x[1] = y1; x[3] = y3;
    float c2, s2, c3, s3;
    __sincosf(0.5f * p[2], &s2, &c2);
    __sincosf(0.5f * p[3], &s3, &c3);
    float2 t00 = cadd(csc(c3, x[0]), csc(-s3, x[1]));
    float2 t01 = cadd(csc(s3, x[0]), csc( c3, x[1]));
    float2 t10 = cadd(csc(c3, x[2]), csc(-s3, x[3]));
    float2 t11 = cadd(csc(s3, x[2]), csc( c3, x[3]));
    x[0] = cadd(csc(c2, t00), csc(-s2, t10));
    x[1] = cadd(csc(c2, t01), csc(-s2, t11));
    x[2] = cadd(csc(s2, t00), csc( c2, t10));
    x[3] = cadd(csc(s2, t01), csc( c2, t11));
    float c1, s1;
    __sincosf(0.5f * p[1], &s1, &c1);
    float2 u00 = cadd(csc(c1, x[0]), cni(s1, x[1]));
    float2 u01 = cadd(cni(s1, x[0]), csc(c1, x[1]));
    float2 u10 = cadd(csc(c1, x[2]), cni(s1, x[3]));
    float2 u11 = cadd(cni(s1, x[2]), csc(c1, x[3]));
    x[0] = cadd(csc(c1, u00), cni(s1, u10));
    x[1] = cadd(csc(c1, u01), cni(s1, u11));
    x[2] = cadd(cni(s1, u00), csc(c1, u10));
    x[3] = cadd(cni(s1, u01), csc(c1, u11));
}
__device__ __forceinline__ float fidelity_from(const float* l1, const float* l2) {
    float2 s1[4] = {make_float2(1.f, 0.f), make_float2(0.f, 0.f),
                    make_float2(0.f, 0.f), make_float2(0.f, 0.f)};
    applyU(l1, s1);
    applyU(l1 + 5, s1);
    float2 s2[4] = {make_float2(1.f, 0.f), make_float2(0.f, 0.f),
                    make_float2(0.f, 0.f), make_float2(0.f, 0.f)};
    applyU(l2, s2);
    applyU(l2 + 5, s2);
    float re = 0.f, im = 0.f;
    #pragma unroll
    for (int i = 0; i < 4; i++) {
        re += s2[i].x * s1[i].x + s2[i].y * s1[i].y;
        im += s2[i].x * s1[i].y - s2[i].y * s1[i].x;
    }
    return re * re + im * im;
}

// ---------------------------------------------------------------------------
// tf32 GEMM (round-13 structure and compute order, verbatim).
// ---------------------------------------------------------------------------
template<int NWT, int OMODE, bool YSPLIT>
__global__ __launch_bounds__(256, 2)
void gemm_tf32(const float* __restrict__ A,
               const unsigned char* __restrict__ Wf,
               const float* __restrict__ bias, void* __restrict__ Out,
               int Ntrue, int K, int nch, int w_rowb,
               const float* __restrict__ W4, const float* __restrict__ b4) {
    extern __shared__ __align__(16) char sm[];
    constexpr int NTC   = NWT * 16;
    constexpr int ABY   = 128 * ASTR * 4;     // 18432
    constexpr int STAGE = ABY + NTC * 128;
    constexpr int CSS   = 68;

    const uint32_t sb = smem_u32(sm);
    const int tid  = threadIdx.x;
    const int wid  = tid >> 5;
    const int lane = tid & 31;
    const int g    = lane >> 2;
    const int t    = lane & 3;
    const int mw   = wid & 3;
    const int nw   = wid >> 2;
    const int bx   = blockIdx.x;
    const size_t m0 = (size_t)(YSPLIT ? (bx >> 1) : bx) * 128;
    const int n0   = YSPLIT ? (bx & 1) * NTC : 0;

    float acc[2][NWT][4];
    #pragma unroll
    for (int mt = 0; mt < 2; mt++)
        #pragma unroll
        for (int j = 0; j < NWT; j++)
            #pragma unroll
            for (int p = 0; p < 4; p++) acc[mt][j][p] = 0.f;

    auto stage = [&](int c, int slot) {
        const uint32_t bufb = sb + slot * STAGE;
        #pragma unroll
        for (int i = 0; i < 4; i++) {
            int f = tid + i * 256;
            int row = f >> 3, j = f & 7;
            int k0 = c * 32 + j * 4;
            int sz = (k0 + 4 <= K) ? 16 : 0;
            const float* src = A + (m0 + row) * (size_t)K + (sz ? k0 : 0);
            cpa16z(bufb + row * 144 + j * 16, src, sz);
        }
        #pragma unroll
        for (int i = 0; i < (NTC * 8 + 255) / 256; i++) {
            int f = tid + i * 256;
            if (f < NTC * 8) {
                int row = f >> 3, e = f & 7;
                cpa16(bufb + ABY + row * 128 + 16 * (e ^ ((row & 1) * 4)),
                      Wf + (size_t)(n0 + row) * w_rowb + c * 128 + e * 16);
            }
        }
    };
    auto compute = [&](int slot) {
        const uint32_t* Asu = (const uint32_t*)(sm + slot * STAGE);
        const char*     Ws  = sm + slot * STAGE + ABY;
        const uint32_t* rb0 = Asu + (mw * 32 +      g) * ASTR + t;
        const uint32_t* rb1 = Asu + (mw * 32 +  8 + g) * ASTR + t;
        const uint32_t* rb2 = Asu + (mw * 32 + 16 + g) * ASTR + t;
        const uint32_t* rb3 = Asu + (mw * 32 + 24 + g) * ASTR + t;
        #pragma unroll
        for (int s = 0; s < 2; s++) {
            uint32_t ua[4][4];
            #pragma unroll
            for (int q = 0; q < 4; q++) {
                ua[0][q] = rb0[16 * s + 4 * q];
                ua[1][q] = rb1[16 * s + 4 * q];
                ua[2][q] = rb2[16 * s + 4 * q];
                ua[3][q] = rb3[16 * s + 4 * q];
            }
            #pragma unroll
            for (int j = 0; j < NWT; j++) {
                int wr = (nw * NWT + j) * 8 + g;
                uint4 bb = *(const uint4*)(Ws + wr * 128 +
                                           16 * ((s * 4 + t) ^ ((wr & 1) * 4)));
                mma_tf32(acc[0][j], ua[0][0], ua[1][0], ua[0][1], ua[1][1], bb.x, bb.y);
                mma_tf32(acc[1][j], ua[2][0], ua[3][0], ua[2][1], ua[3][1], bb.x, bb.y);
                mma_tf32(acc[0][j], ua[0][2], ua[1][2], ua[0][3], ua[1][3], bb.z, bb.w);
                mma_tf32(acc[1][j], ua[2][2], ua[3][2], ua[2][3], ua[3][3], bb.z, bb.w);
            }
        }
    };

    stage(0, 0); CP_COMMIT();
    stage(1, 1); CP_COMMIT();
    for (int c = 0; c < nch; ++c) {
        if (c + 1 < nch) { CP_WAIT1(); } else { CP_WAIT0(); }
        __syncthreads();
        compute(c - (c / 3) * 3);
        if (c + 2 < nch) { stage(c + 2, (c + 2) % 3); CP_COMMIT(); }
    }
    __syncthreads();

    if constexpr (OMODE == 0) {
        float* C = (float*)Out;
        #pragma unroll
        for (int mt = 0; mt < 2; mt++) {
            const size_t r = m0 + mw * 32 + mt * 16 + g;
            #pragma unroll
            for (int j = 0; j < NWT; j++) {
                int n = n0 + (nw * NWT + j) * 8 + 2 * t;
                if (n < Ntrue) {
                    float2 b2 = *(const float2*)(bias + n);
                    float v0 = fmaxf(acc[mt][j][0] + b2.x, 0.f);
                    float v1 = fmaxf(acc[mt][j][1] + b2.y, 0.f);
                    float v2 = fmaxf(acc[mt][j][2] + b2.x, 0.f);
                    float v3 = fmaxf(acc[mt][j][3] + b2.y, 0.f);
                    *(float2*)(C + r * Ntrue + n)       = make_float2(v0, v1);
                    *(float2*)(C + (r + 8) * Ntrue + n) = make_float2(v2, v3);
                }
            }
        }
    } else {
        float* Cs = (float*)sm;
        #pragma unroll
        for (int mt = 0; mt < 2; mt++) {
            int r = mw * 32 + mt * 16 + g;
            #pragma unroll
            for (int j = 0; j < NWT; j++) {
                int nl = (nw * NWT + j) * 8 + 2 * t;
                float bx2 = (nl     < Ntrue) ? bias[nl]     : 0.f;
                float by2 = (nl + 1 < Ntrue) ? bias[nl + 1] : 0.f;
                float v0 = fmaxf(acc[mt][j][0] + bx2, 0.f);
                float v1 = fmaxf(acc[mt][j][1] + by2, 0.f);
                float v2 = fmaxf(acc[mt][j][2] + bx2, 0.f);
                float v3 = fmaxf(acc[mt][j][3] + by2, 0.f);
                *(float2*)(Cs + r * CSS + nl)       = make_float2(v0, v1);
                *(float2*)(Cs + (r + 8) * CSS + nl) = make_float2(v2, v3);
            }
        }
        float* w4s = (float*)(sm + 128 * CSS * 4);
        float* b4s = w4s + 500;
        float* Ls  = (float*)(sm + 128 * CSS * 4 + 2048);
        for (int i = tid; i < 500; i += 256) w4s[i] = W4[i];
        if (tid < 10) b4s[tid] = b4[tid];
        __syncthreads();

        if (tid < 128) {
            float l[10];
            #pragma unroll
            for (int j = 0; j < 10; j++) l[j] = b4s[j];
            #pragma unroll 5
            for (int k = 0; k < 50; k++) {
                float hv = Cs[tid * CSS + k];
                #pragma unroll
                for (int j = 0; j < 10; j++) l[j] = fmaf(w4s[j * 50 + k], hv, l[j]);
            }
            #pragma unroll
            for (int j = 0; j < 10; j++) Ls[tid * 11 + j] = l[j];
        }
        __syncthreads();
        if (tid < 64) {
            ((float*)Out)[(size_t)blockIdx.x * 64 + tid] =
                fidelity_from(Ls + 2 * tid * 11, Ls + (2 * tid + 1) * 11);
        }
    }
}

// ---------------------------------------------------------------------------
extern "C" void kernel_launch(void* const* d_in, const int* in_sizes, int n_in,
                              void* d_out, int out_size) {
    const float* x  = (const float*)d_in[0];
    const float* W1 = (const float*)d_in[1];
    const float* b1 = (const float*)d_in[2];
    const float* W2 = (const float*)d_in[3];
    const float* b2 = (const float*)d_in[4];
    const float* W3 = (const float*)d_in[5];
    const float* b3 = (const float*)d_in[6];
    const float* W4 = (const float*)d_in[7];
    const float* b4 = (const float*)d_in[8];

    float *h1, *h2;
    unsigned char *w1f, *w2f, *w3f;
    cudaGetSymbolAddress((void**)&h1,  g_h1);
    cudaGetSymbolAddress((void**)&h2,  g_h2);
    cudaGetSymbolAddress((void**)&w1f, g_w1f);
    cudaGetSymbolAddress((void**)&w2f, g_w2f);
    cudaGetSymbolAddress((void**)&w3f, g_w3f);

    // Single merged prep launch (6560 work items)
    prep_all<<<(6560 + 255) / 256, 256>>>(W1, W2, W3, w1f, w2f, w3f);

    constexpr int SM12 = 3 * (128 * 144 + 112 * 128);  // 98304
    constexpr int SM3  = 3 * (128 * 144 + 64  * 128);  // 79872
    cudaFuncSetAttribute(gemm_tf32<7, 0, true>,
                         cudaFuncAttributeMaxDynamicSharedMemorySize, SM12);
    cudaFuncSetAttribute(gemm_tf32<7, 0, false>,
                         cudaFuncAttributeMaxDynamicSharedMemorySize, SM12);
    cudaFuncSetAttribute(gemm_tf32<4, 2, false>,
                         cudaFuncAttributeMaxDynamicSharedMemorySize, SM3);

    const int MT = MROWS / 128;   // 1024
    // L1: A = x [2B,300] fp32, y-interleaved split (NTC=112 covers 224>=200)
    gemm_tf32<7, 0, true ><<<MT * 2, 256, SM12>>>(x,  w1f, b1, h1,
                                                  200, 300, 10, 1280, W4, b4);
    // L2: A = h1 [M,200] fp32, NTC=112 covers 100
    gemm_tf32<7, 0, false><<<MT,     256, SM12>>>(h1, w2f, b2, h2,
                                                  100, 200, 7, 896, W4, b4);
    // L3: A = h2 [M,100] fp32, NTC=64 covers 50, fused layer4 + fidelity
    gemm_tf32<4, 2, false><<<MT,     256, SM3 >>>(h2, w3f, b3, d_out,
                                                  50, 100, 4, 512, W4, b4);
}

// round 16
// speedup vs baseline: 1.1942x; 1.0596x over previous
#include <cuda_runtime.h>
#include <math.h>
#include <cstdint>

// ---------------------------------------------------------------------------
// PreQ round 16: R15 (best: 199.2us) + L3/L4/quantum folded into L2 epilogue.
//  - L1: x -> h1 (unchanged, y-interleaved split, 3-stage ring)
//  - L2-fused: h1 -> h2 in SMEM -> L3 (W3 resident) -> layer4 -> fidelity
//    (kills the 35us L3 kernel + the 105MB h2 round-trip)
//  - A fragments raw fp32 bits, W RN frag images, merged single prep launch
// ---------------------------------------------------------------------------

#define MROWS 131072   // 2 * 65536
#define ASTR  36       // A smem row stride in floats (144B)

__device__ float g_h1[(size_t)MROWS * 200];
__device__ __align__(16) unsigned char g_w1f[224 * 1280];
__device__ __align__(16) unsigned char g_w2f[112 * 896];
__device__ __align__(16) unsigned char g_w3f[64 * 512];

// ---------------- helpers ----------------
__device__ __forceinline__ uint32_t smem_u32(const void* p) {
    uint32_t a;
    asm("{ .reg .u64 t; cvta.to.shared.u64 t, %1; cvt.u32.u64 %0, t; }"
        : "=r"(a) : "l"(p));
    return a;
}
__device__ __forceinline__ void cpa16(uint32_t dst, const void* src) {
    asm volatile("cp.async.cg.shared.global [%0], [%1], 16;"
                 :: "r"(dst), "l"(src) : "memory");
}
__device__ __forceinline__ void cpa16z(uint32_t dst, const void* src, int sz) {
    asm volatile("cp.async.cg.shared.global [%0], [%1], 16, %2;"
                 :: "r"(dst), "l"(src), "r"(sz) : "memory");
}
#define CP_COMMIT() asm volatile("cp.async.commit_group;" ::: "memory")
#define CP_WAIT0()  asm volatile("cp.async.wait_group 0;" ::: "memory")
#define CP_WAIT1()  asm volatile("cp.async.wait_group 1;" ::: "memory")

__device__ __forceinline__ uint32_t to_tf32(float f) {
    uint32_t r;
    asm("cvt.rna.tf32.f32 %0, %1;" : "=r"(r) : "f"(f));
    return r;
}
__device__ __forceinline__ void mma_tf32(float c[4],
                                         uint32_t a0, uint32_t a1,
                                         uint32_t a2, uint32_t a3,
                                         uint32_t b0, uint32_t b1) {
    asm volatile(
        "mma.sync.aligned.m16n8k8.row.col.f32.tf32.tf32.f32 "
        "{%0,%1,%2,%3}, {%4,%5,%6,%7}, {%8,%9}, {%0,%1,%2,%3};"
        : "+f"(c[0]), "+f"(c[1]), "+f"(c[2]), "+f"(c[3])
        : "r"(a0), "r"(a1), "r"(a2), "r"(a3), "r"(b0), "r"(b1));
}

// ---------------------------------------------------------------------------
// Merged prep: all three W frag images in ONE launch (validated R14/R15).
// ---------------------------------------------------------------------------
__device__ __forceinline__ void prep_one(const float* S, unsigned char* D,
                                         int src_rows, int K, int nblk, int f) {
    int row = f / nblk, eb = f - row * nblk;
    int k0 = eb * 16;
    float v[16];
    #pragma unroll
    for (int i = 0; i < 16; i++) v[i] = 0.f;
    if (row < src_rows) {
        #pragma unroll
        for (int i = 0; i < 4; i++) {
            int k = k0 + i * 4;
            if (k < K) {
                float4 q = *(const float4*)(S + (size_t)row * K + k);
                v[i * 4 + 0] = q.x; v[i * 4 + 1] = q.y;
                v[i * 4 + 2] = q.z; v[i * 4 + 3] = q.w;
            }
        }
    }
    uint32_t u[16];
    #pragma unroll
    for (int i = 0; i < 16; i++) u[i] = to_tf32(v[i]);
    unsigned char* dst = D + (size_t)row * (nblk * 64) + (size_t)eb * 64;
    #pragma unroll
    for (int tp = 0; tp < 4; tp++)
        *(uint4*)(dst + tp * 16) =
            make_uint4(u[tp], u[tp + 4], u[tp + 8], u[tp + 12]);
}

__global__ void prep_all(const float* __restrict__ W1,
                         const float* __restrict__ W2,
                         const float* __restrict__ W3,
                         unsigned char* __restrict__ w1f,
                         unsigned char* __restrict__ w2f,
                         unsigned char* __restrict__ w3f) {
    constexpr int N1 = 224 * 20;            // 4480
    constexpr int N2 = N1 + 112 * 14;       // 6048
    constexpr int N3 = N2 + 64 * 8;         // 6560
    int f = blockIdx.x * blockDim.x + threadIdx.x;
    if (f < N1)      prep_one(W1, w1f, 200, 300, 20, f);
    else if (f < N2) prep_one(W2, w2f, 100, 200, 14, f - N1);
    else if (f < N3) prep_one(W3, w3f, 50,  100, 8,  f - N2);
}

// ---------------- quantum math (verified rounds 1-15) ----------------
__device__ __forceinline__ float2 cadd(float2 a, float2 b) {
    return make_float2(a.x + b.x, a.y + b.y);
}
__device__ __forceinline__ float2 csc(float s, float2 a) {
    return make_float2(s * a.x, s * a.y);
}
__device__ __forceinline__ float2 cni(float s, float2 a) {
    return make_float2(s * a.y, -s * a.x);
}
__device__ void applyU(const float* __restrict__ p, float2 x[4]) {
    float c4, s4;
    __sincosf(0.5f * p[4], &s4, &c4);
    float2 y1 = make_float2(c4 * x[1].x + s4 * x[3].y,
                            c4 * x[1].y - s4 * x[3].x);
    float2 y3 = make_float2(s4 * x[1].y + c4 * x[3].x,
                           -s4 * x[1].x + c4 * x[3].y);
    x[1] = y1; x[3] = y3;
    float c2, s2, c3, s3;
    __sincosf(0.5f * p[2], &s2, &c2);
    __sincosf(0.5f * p[3], &s3, &c3);
    float2 t00 = cadd(csc(c3, x[0]), csc(-s3, x[1]));
    float2 t01 = cadd(csc(s3, x[0]), csc( c3, x[1]));
    float2 t10 = cadd(csc(c3, x[2]), csc(-s3, x[3]));
    float2 t11 = cadd(csc(s3, x[2]), csc( c3, x[3]));
    x[0] = cadd(csc(c2, t00), csc(-s2, t10));
    x[1] = cadd(csc(c2, t01), csc(-s2, t11));
    x[2] = cadd(csc(s2, t00), csc( c2, t10));
    x[3] = cadd(csc(s2, t01), csc( c2, t11));
    float c1, s1;
    __sincosf(0.5f * p[1], &s1, &c1);
    float2 u00 = cadd(csc(c1, x[0]), cni(s1, x[1]));
    float2 u01 = cadd(cni(s1, x[0]), csc(c1, x[1]));
    float2 u10 = cadd(csc(c1, x[2]), cni(s1, x[3]));
    float2 u11 = cadd(cni(s1, x[2]), csc(c1, x[3]));
    x[0] = cadd(csc(c1, u00), cni(s1, u10));
    x[1] = cadd(csc(c1, u01), cni(s1, u11));
    x[2] = cadd(cni(s1, u00), csc(c1, u10));
    x[3] = cadd(cni(s1, u01), csc(c1, u11));
}
__device__ __forceinline__ float fidelity_from(const float* l1, const float* l2) {
    float2 s1[4] = {make_float2(1.f, 0.f), make_float2(0.f, 0.f),
                    make_float2(0.f, 0.f), make_float2(0.f, 0.f)};
    applyU(l1, s1);
    applyU(l1 + 5, s1);
    float2 s2[4] = {make_float2(1.f, 0.f), make_float2(0.f, 0.f),
                    make_float2(0.f, 0.f), make_float2(0.f, 0.f)};
    applyU(l2, s2);
    applyU(l2 + 5, s2);
    float re = 0.f, im = 0.f;
    #pragma unroll
    for (int i = 0; i < 4; i++) {
        re += s2[i].x * s1[i].x + s2[i].y * s1[i].y;
        im += s2[i].x * s1[i].y - s2[i].y * s1[i].x;
    }
    return re * re + im * im;
}

// ---------------------------------------------------------------------------
// L1 GEMM (R13/R15 structure, verbatim): 128 rows/CTA, NWT=7 (NTC=112),
// y-interleaved N-split, 3-stage ring, fp32 out + ReLU.
// ---------------------------------------------------------------------------
__global__ __launch_bounds__(256, 2)
void gemm_l1(const float* __restrict__ A,
             const unsigned char* __restrict__ Wf,
             const float* __restrict__ bias, float* __restrict__ C) {
    extern __shared__ __align__(16) char sm[];
    constexpr int NWT   = 7;
    constexpr int NTC   = 112;
    constexpr int ABY   = 128 * ASTR * 4;     // 18432
    constexpr int STAGE = ABY + NTC * 128;    // 32768
    constexpr int K = 300, Ntrue = 200, nch = 10, w_rowb = 1280;

    const uint32_t sb = smem_u32(sm);
    const int tid  = threadIdx.x;
    const int wid  = tid >> 5;
    const int lane = tid & 31;
    const int g    = lane >> 2;
    const int t    = lane & 3;
    const int mw   = wid & 3;
    const int nw   = wid >> 2;
    const int bx   = blockIdx.x;
    const size_t m0 = (size_t)(bx >> 1) * 128;
    const int n0   = (bx & 1) * NTC;

    float acc[2][NWT][4];
    #pragma unroll
    for (int mt = 0; mt < 2; mt++)
        #pragma unroll
        for (int j = 0; j < NWT; j++)
            #pragma unroll
            for (int p = 0; p < 4; p++) acc[mt][j][p] = 0.f;

    auto stage = [&](int c, int slot) {
        const uint32_t bufb = sb + slot * STAGE;
        #pragma unroll
        for (int i = 0; i < 4; i++) {
            int f = tid + i * 256;
            int row = f >> 3, j = f & 7;
            int k0 = c * 32 + j * 4;
            int sz = (k0 + 4 <= K) ? 16 : 0;
            const float* src = A + (m0 + row) * (size_t)K + (sz ? k0 : 0);
            cpa16z(bufb + row * 144 + j * 16, src, sz);
        }
        #pragma unroll
        for (int i = 0; i < (NTC * 8 + 255) / 256; i++) {
            int f = tid + i * 256;
            if (f < NTC * 8) {
                int row = f >> 3, e = f & 7;
                cpa16(bufb + ABY + row * 128 + 16 * (e ^ ((row & 1) * 4)),
                      Wf + (size_t)(n0 + row) * w_rowb + c * 128 + e * 16);
            }
        }
    };
    auto compute = [&](int slot) {
        const uint32_t* Asu = (const uint32_t*)(sm + slot * STAGE);
        const char*     Ws  = sm + slot * STAGE + ABY;
        const uint32_t* rb0 = Asu + (mw * 32 +      g) * ASTR + t;
        const uint32_t* rb1 = Asu + (mw * 32 +  8 + g) * ASTR + t;
        const uint32_t* rb2 = Asu + (mw * 32 + 16 + g) * ASTR + t;
        const uint32_t* rb3 = Asu + (mw * 32 + 24 + g) * ASTR + t;
        #pragma unroll
        for (int s = 0; s < 2; s++) {
            uint32_t ua[4][4];
            #pragma unroll
            for (int q = 0; q < 4; q++) {
                ua[0][q] = rb0[16 * s + 4 * q];
                ua[1][q] = rb1[16 * s + 4 * q];
                ua[2][q] = rb2[16 * s + 4 * q];
                ua[3][q] = rb3[16 * s + 4 * q];
            }
            #pragma unroll
            for (int j = 0; j < NWT; j++) {
                int wr = (nw * NWT + j) * 8 + g;
                uint4 bb = *(const uint4*)(Ws + wr * 128 +
                                           16 * ((s * 4 + t) ^ ((wr & 1) * 4)));
                mma_tf32(acc[0][j], ua[0][0], ua[1][0], ua[0][1], ua[1][1], bb.x, bb.y);
                mma_tf32(acc[1][j], ua[2][0], ua[3][0], ua[2][1], ua[3][1], bb.x, bb.y);
                mma_tf32(acc[0][j], ua[0][2], ua[1][2], ua[0][3], ua[1][3], bb.z, bb.w);
                mma_tf32(acc[1][j], ua[2][2], ua[3][2], ua[2][3], ua[3][3], bb.z, bb.w);
            }
        }
    };

    stage(0, 0); CP_COMMIT();
    stage(1, 1); CP_COMMIT();
    for (int c = 0; c < nch; ++c) {
        if (c + 1 < nch) { CP_WAIT1(); } else { CP_WAIT0(); }
        __syncthreads();
        compute(c - (c / 3) * 3);
        if (c + 2 < nch) { stage(c + 2, (c + 2) % 3); CP_COMMIT(); }
    }
    __syncthreads();

    #pragma unroll
    for (int mt = 0; mt < 2; mt++) {
        const size_t r = m0 + mw * 32 + mt * 16 + g;
        #pragma unroll
        for (int j = 0; j < NWT; j++) {
            int n = n0 + (nw * NWT + j) * 8 + 2 * t;
            if (n < Ntrue) {
                float2 b2 = *(const float2*)(bias + n);
                float v0 = fmaxf(acc[mt][j][0] + b2.x, 0.f);
                float v1 = fmaxf(acc[mt][j][1] + b2.y, 0.f);
                float v2 = fmaxf(acc[mt][j][2] + b2.x, 0.f);
                float v3 = fmaxf(acc[mt][j][3] + b2.y, 0.f);
                *(float2*)(C + r * Ntrue + n)       = make_float2(v0, v1);
                *(float2*)(C + (r + 8) * Ntrue + n) = make_float2(v2, v3);
            }
        }
    }
}

// ---------------------------------------------------------------------------
// L2-fused: h1 -> h2 (SMEM) -> L3 (W3 resident) -> layer4 -> fidelity.
// 128 rows/CTA, grid = MROWS/128, NWT=7 covers all 100 h2 cols per CTA.
// SMEM: ring [0, 98304) during L2 loop. After loop (ring dead):
//   h2s   [0, 67584)        128 x 132 fp32 (stride 132 -> conflict-free)
//   W3s   [67584, 100352)   64 rows x 4 chunks x 128B
// After L3 (h2s dead):
//   Cs    [0, 34816)        128 x 68 fp32
//   w4s/b4s [34816, 36864), Ls [36864, 42496)  (aliases dead h2s region)
// ---------------------------------------------------------------------------
#define F_W3OFF 67584
#define F_SMEM  100352

__global__ __launch_bounds__(256, 2)
void gemm_l2_fused(const float* __restrict__ A,
                   const unsigned char* __restrict__ w2f,
                   const unsigned char* __restrict__ w3f,
                   const float* __restrict__ b2, const float* __restrict__ b3,
                   const float* __restrict__ W4, const float* __restrict__ b4,
                   float* __restrict__ out) {
    extern __shared__ __align__(16) char sm[];
    constexpr int NWT   = 7;
    constexpr int NTC   = 112;
    constexpr int ABY   = 128 * ASTR * 4;     // 18432
    constexpr int STAGE = ABY + NTC * 128;    // 32768
    constexpr int K = 200, nch = 7, w_rowb = 896;
    constexpr int H2S = 132;                  // h2s row stride (floats)
    constexpr int CSS = 68;

    const uint32_t sb = smem_u32(sm);
    const int tid  = threadIdx.x;
    const int wid  = tid >> 5;
    const int lane = tid & 31;
    const int g    = lane >> 2;
    const int t    = lane & 3;
    const int mw   = wid & 3;
    const int nw   = wid >> 2;
    const size_t m0 = (size_t)blockIdx.x * 128;

    // ================= L2 main loop (R15 structure) =================
    float acc[2][NWT][4];
    #pragma unroll
    for (int mt = 0; mt < 2; mt++)
        #pragma unroll
        for (int j = 0; j < NWT; j++)
            #pragma unroll
            for (int p = 0; p < 4; p++) acc[mt][j][p] = 0.f;

    auto stage = [&](int c, int slot) {
        const uint32_t bufb = sb + slot * STAGE;
        #pragma unroll
        for (int i = 0; i < 4; i++) {
            int f = tid + i * 256;
            int row = f >> 3, j = f & 7;
            int k0 = c * 32 + j * 4;
            int sz = (k0 + 4 <= K) ? 16 : 0;
            const float* src = A + (m0 + row) * (size_t)K + (sz ? k0 : 0);
            cpa16z(bufb + row * 144 + j * 16, src, sz);
        }
        #pragma unroll
        for (int i = 0; i < (NTC * 8 + 255) / 256; i++) {
            int f = tid + i * 256;
            if (f < NTC * 8) {
                int row = f >> 3, e = f & 7;
                cpa16(bufb + ABY + row * 128 + 16 * (e ^ ((row & 1) * 4)),
                      w2f + (size_t)row * w_rowb + c * 128 + e * 16);
            }
        }
    };
    auto compute = [&](int slot) {
        const uint32_t* Asu = (const uint32_t*)(sm + slot * STAGE);
        const char*     Ws  = sm + slot * STAGE + ABY;
        const uint32_t* rb0 = Asu + (mw * 32 +      g) * ASTR + t;
        const uint32_t* rb1 = Asu + (mw * 32 +  8 + g) * ASTR + t;
        const uint32_t* rb2 = Asu + (mw * 32 + 16 + g) * ASTR + t;
        const uint32_t* rb3 = Asu + (mw * 32 + 24 + g) * ASTR + t;
        #pragma unroll
        for (int s = 0; s < 2; s++) {
            uint32_t ua[4][4];
            #pragma unroll
            for (int q = 0; q < 4; q++) {
                ua[0][q] = rb0[16 * s + 4 * q];
                ua[1][q] = rb1[16 * s + 4 * q];
                ua[2][q] = rb2[16 * s + 4 * q];
                ua[3][q] = rb3[16 * s + 4 * q];
            }
            #pragma unroll
            for (int j = 0; j < NWT; j++) {
                int wr = (nw * NWT + j) * 8 + g;
                uint4 bb = *(const uint4*)(Ws + wr * 128 +
                                           16 * ((s * 4 + t) ^ ((wr & 1) * 4)));
                mma_tf32(acc[0][j], ua[0][0], ua[1][0], ua[0][1], ua[1][1], bb.x, bb.y);
                mma_tf32(acc[1][j], ua[2][0], ua[3][0], ua[2][1], ua[3][1], bb.x, bb.y);
                mma_tf32(acc[0][j], ua[0][2], ua[1][2], ua[0][3], ua[1][3], bb.z, bb.w);
                mma_tf32(acc[1][j], ua[2][2], ua[3][2], ua[2][3], ua[3][3], bb.z, bb.w);
            }
        }
    };

    stage(0, 0); CP_COMMIT();
    stage(1, 1); CP_COMMIT();
    for (int c = 0; c < nch; ++c) {
        if (c + 1 < nch) { CP_WAIT1(); } else { CP_WAIT0(); }
        __syncthreads();
        compute(c - (c / 3) * 3);
        if (c + 2 < nch) { stage(c + 2, (c + 2) % 3); CP_COMMIT(); }
    }
    __syncthreads();   // ring dead below this point

    // ====== stage W3 (resident, overlaps h2s writes) + write h2s ======
    {
        // 64 rows x 4 chunks x 8 entries = 2048 cpa16, 8 per thread
        #pragma unroll
        for (int i = 0; i < 8; i++) {
            int f = tid + i * 256;
            int c = f >> 9, rem = f & 511;
            int row = rem >> 3, e = rem & 7;
            cpa16(sb + F_W3OFF + c * 8192 + row * 128 + 16 * (e ^ ((row & 1) * 4)),
                  w3f + (size_t)row * 512 + c * 128 + e * 16);
        }
        CP_COMMIT();
    }
    float* h2s = (float*)sm;
    #pragma unroll
    for (int mt = 0; mt < 2; mt++) {
        int r = mw * 32 + mt * 16 + g;
        #pragma unroll
        for (int j = 0; j < NWT; j++) {
            int nl = (nw * NWT + j) * 8 + 2 * t;
            float bx2 = (nl     < 100) ? b2[nl]     : 0.f;
            float by2 = (nl + 1 < 100) ? b2[nl + 1] : 0.f;
            float v0 = (nl     < 100) ? fmaxf(acc[mt][j][0] + bx2, 0.f) : 0.f;
            float v1 = (nl + 1 < 100) ? fmaxf(acc[mt][j][1] + by2, 0.f) : 0.f;
            float v2 = (nl     < 100) ? fmaxf(acc[mt][j][2] + bx2, 0.f) : 0.f;
            float v3 = (nl + 1 < 100) ? fmaxf(acc[mt][j][3] + by2, 0.f) : 0.f;
            *(float2*)(h2s + r * H2S + nl)       = make_float2(v0, v1);
            *(float2*)(h2s + (r + 8) * H2S + nl) = make_float2(v2, v3);
        }
    }
    // zero cols 112..127 (128 rows x 16 cols = 1024 float2, 4 per thread)
    #pragma unroll
    for (int i = 0; i < 4; i++) {
        int f = tid + i * 256;
        int row = f >> 3, q = f & 7;
        *(float2*)(h2s + row * H2S + 112 + 2 * q) = make_float2(0.f, 0.f);
    }
    CP_WAIT0();
    __syncthreads();

    // ================= L3: K=128 from h2s, N=64 (NWT3=4) =================
    float acc3[2][4][4];
    #pragma unroll
    for (int mt = 0; mt < 2; mt++)
        #pragma unroll
        for (int j = 0; j < 4; j++)
            #pragma unroll
            for (int p = 0; p < 4; p++) acc3[mt][j][p] = 0.f;

    const char* W3s = sm + F_W3OFF;
    const uint32_t* h2u = (const uint32_t*)h2s;
    #pragma unroll
    for (int c = 0; c < 4; ++c) {
        #pragma unroll
        for (int s = 0; s < 2; s++) {
            uint32_t ua[4][4];
            #pragma unroll
            for (int ri = 0; ri < 4; ri++) {
                const uint32_t* rb = h2u + (mw * 32 + 8 * ri + g) * H2S +
                                     c * 32 + s * 16 + t;
                #pragma unroll
                for (int q = 0; q < 4; q++)
                    ua[ri][q] = rb[4 * q];    // raw bits -> tf32 truncation
            }
            #pragma unroll
            for (int j = 0; j < 4; j++) {
                int wr = (nw * 4 + j) * 8 + g;
                uint4 bb = *(const uint4*)(W3s + c * 8192 + wr * 128 +
                                           16 * ((s * 4 + t) ^ ((wr & 1) * 4)));
                mma_tf32(acc3[0][j], ua[0][0], ua[1][0], ua[0][1], ua[1][1], bb.x, bb.y);
                mma_tf32(acc3[1][j], ua[2][0], ua[3][0], ua[2][1], ua[3][1], bb.x, bb.y);
                mma_tf32(acc3[0][j], ua[0][2], ua[1][2], ua[0][3], ua[1][3], bb.z, bb.w);
                mma_tf32(acc3[1][j], ua[2][2], ua[3][2], ua[2][3], ua[3][3], bb.z, bb.w);
            }
        }
    }
    __syncthreads();   // h2s dead; Cs aliases it

    // L3 epilogue -> Cs (bias + relu)
    float* Cs = (float*)sm;
    #pragma unroll
    for (int mt = 0; mt < 2; mt++) {
        int r = mw * 32 + mt * 16 + g;
        #pragma unroll
        for (int j = 0; j < 4; j++) {
            int nl = (nw * 4 + j) * 8 + 2 * t;
            float bx2 = (nl     < 50) ? b3[nl]     : 0.f;
            float by2 = (nl + 1 < 50) ? b3[nl + 1] : 0.f;
            *(float2*)(Cs + r * CSS + nl) =
                make_float2(fmaxf(acc3[mt][j][0] + bx2, 0.f),
                            fmaxf(acc3[mt][j][1] + by2, 0.f));
            *(float2*)(Cs + (r + 8) * CSS + nl) =
                make_float2(fmaxf(acc3[mt][j][2] + bx2, 0.f),
                            fmaxf(acc3[mt][j][3] + by2, 0.f));
        }
    }

    // ================= layer4 (50->10) + fidelity =================
    float* w4s = (float*)(sm + 128 * CSS * 4);          // 500
    float* b4s = w4s + 500;                             // 10
    float* Ls  = (float*)(sm + 128 * CSS * 4 + 2048);   // [128][11]
    for (int i = tid; i < 500; i += 256) w4s[i] = W4[i];
    if (tid < 10) b4s[tid] = b4[tid];
    __syncthreads();

    if (tid < 128) {
        float l[10];
        #pragma unroll
        for (int j = 0; j < 10; j++) l[j] = b4s[j];
        #pragma unroll 5
        for (int k = 0; k < 50; k++) {
            float hv = Cs[tid * CSS + k];
            #pragma unroll
            for (int j = 0; j < 10; j++) l[j] = fmaf(w4s[j * 50 + k], hv, l[j]);
        }
        #pragma unroll
        for (int j = 0; j < 10; j++) Ls[tid * 11 + j] = l[j];
    }
    __syncthreads();
    if (tid < 64) {
        out[(size_t)blockIdx.x * 64 + tid] =
            fidelity_from(Ls + 2 * tid * 11, Ls + (2 * tid + 1) * 11);
    }
}

// ---------------------------------------------------------------------------
extern "C" void kernel_launch(void* const* d_in, const int* in_sizes, int n_in,
                              void* d_out, int out_size) {
    const float* x  = (const float*)d_in[0];
    const float* W1 = (const float*)d_in[1];
    const float* b1 = (const float*)d_in[2];
    const float* W2 = (const float*)d_in[3];
    const float* b2 = (const float*)d_in[4];
    const float* W3 = (const float*)d_in[5];
    const float* b3 = (const float*)d_in[6];
    const float* W4 = (const float*)d_in[7];
    const float* b4 = (const float*)d_in[8];

    float* h1;
    unsigned char *w1f, *w2f, *w3f;
    cudaGetSymbolAddress((void**)&h1,  g_h1);
    cudaGetSymbolAddress((void**)&w1f, g_w1f);
    cudaGetSymbolAddress((void**)&w2f, g_w2f);
    cudaGetSymbolAddress((void**)&w3f, g_w3f);

    prep_all<<<(6560 + 255) / 256, 256>>>(W1, W2, W3, w1f, w2f, w3f);

    constexpr int SML1 = 3 * (128 * 144 + 112 * 128);  // 98304
    cudaFuncSetAttribute(gemm_l1,
                         cudaFuncAttributeMaxDynamicSharedMemorySize, SML1);
    cudaFuncSetAttribute(gemm_l2_fused,
                         cudaFuncAttributeMaxDynamicSharedMemorySize, F_SMEM);

    const int MT = MROWS / 128;   // 1024
    gemm_l1<<<MT * 2, 256, SML1>>>(x, w1f, b1, h1);
    gemm_l2_fused<<<MT, 256, F_SMEM>>>(h1, w2f, w3f, b2, b3, W4, b4,
                                       (float*)d_out);
}